// round 14
// baseline (speedup 1.0000x reference)
#include <cuda_runtime.h>
#include <cuda_fp16.h>
#include <cstdint>

// x [B=512, T=128, C=512] fp32; Wq/Wk/Wv [H=64, C=512]; out [B, T, 64] fp32.
// Round-14: TWO-KERNEL SPLIT.
//  K1: register-streamed QKV projection (r12 scheme), fp16 Q/K/Vt to global.
//  K2: attention, 128-thr CTAs, warp owns full row-pairs {w,7-w}; P converted
//      D-frag -> A-frag IN REGISTERS (fp16 k-pairs == fp32 D col-pairs).
#define TT 128
#define CC 512
#define HH 64

#define PQH 72    // Q/K smem [128][64] half (36 u32 pitch)
#define PVH 136   // Vt smem [64][128] half (68 u32 pitch)

#define K_QS 0
#define K_KS 18432
#define K_VT 36864
#define K_SMEM 54272

__device__ uint4 Wfg[32 * 12 * 32];     // pre-fragmented fp16 W B-frags
__device__ uint4 Qg4[512 * 1024];       // Q  [b][128][64] fp16
__device__ uint4 Kg4[512 * 1024];       // K  [b][128][64] fp16
__device__ uint4 Vg4[512 * 1024];       // Vt [b][64][128] fp16

__device__ __forceinline__ uint32_t packh(float lo, float hi) {
    __half2 h = __floats2half2_rn(lo, hi);
    return *reinterpret_cast<uint32_t*>(&h);
}
__device__ __forceinline__ uint32_t packh2(float2 v) { return packh(v.x, v.y); }

__device__ __forceinline__ void mma16(float* d, const uint32_t* a, const uint32_t* b) {
    asm volatile(
        "mma.sync.aligned.m16n8k16.row.col.f32.f16.f16.f32 "
        "{%0,%1,%2,%3}, {%4,%5,%6,%7}, {%8,%9}, {%0,%1,%2,%3};"
        : "+f"(d[0]), "+f"(d[1]), "+f"(d[2]), "+f"(d[3])
        : "r"(a[0]), "r"(a[1]), "r"(a[2]), "r"(a[3]), "r"(b[0]), "r"(b[1]));
}

// ------- pre-kernel: W fp32 -> fp16 B-fragments in global -------
__global__ void convwf_kernel(const float* __restrict__ Wq,
                              const float* __restrict__ Wk,
                              const float* __restrict__ Wv)
{
    const int blk  = blockIdx.x;        // ch*12 + np
    const int ch   = blk / 12;
    const int np   = blk % 12;
    const int lane = threadIdx.x;
    const int l4   = lane >> 2;
    const int lk   = lane & 3;
    const int kk   = ch * 16;

    auto wrow = [&](int j) -> const float* {
        return (j < 64) ? (Wq + j * CC)
             : (j < 128) ? (Wk + (j - 64) * CC)
                         : (Wv + (j - 128) * CC);
    };
    const float* r0 = wrow((2 * np) * 8 + l4);
    const float* r1 = wrow((2 * np + 1) * 8 + l4);

    uint4 v;
    v.x = packh2(*reinterpret_cast<const float2*>(r0 + kk + 2 * lk));
    v.y = packh2(*reinterpret_cast<const float2*>(r0 + kk + 2 * lk + 8));
    v.z = packh2(*reinterpret_cast<const float2*>(r1 + kk + 2 * lk));
    v.w = packh2(*reinterpret_cast<const float2*>(r1 + kk + 2 * lk + 8));
    Wfg[blk * 32 + lane] = v;
}

// ============================================================================
// Kernel 1: projection [Q|K|V] = x @ W^T, register-streamed, fp16 out
// ============================================================================
__global__ __launch_bounds__(512, 1)
void proj_kernel(const float* __restrict__ x)
{
    extern __shared__ char smem[];
    __half* Qs = reinterpret_cast<__half*>(smem + K_QS);
    __half* Ks = reinterpret_cast<__half*>(smem + K_KS);
    __half* Vt = reinterpret_cast<__half*>(smem + K_VT);

    const int tid  = threadIdx.x;
    const int wid  = tid >> 5;
    const int lane = tid & 31;
    const int l4   = lane >> 2;
    const int lk   = lane & 3;
    const int b    = blockIdx.x;
    const float* xb = x + (size_t)b * TT * CC;

    const int rtp = (wid >> 1) * 16;
    const int wcp = wid & 1;
    const int nb1 = wcp * 96;

    float acc[12][4];
#pragma unroll
    for (int j = 0; j < 12; j++)
#pragma unroll
        for (int k = 0; k < 4; k++) acc[j][k] = 0.0f;

    const float* xp0 = xb + (rtp + l4) * CC + 2 * lk;
    const float* xp1 = xb + (rtp + 8 + l4) * CC + 2 * lk;
    const uint4* wfp = Wfg + (wcp * 6) * 32 + lane;

    float2 x0[4], x1[4];
    uint4  w0[6], w1[6];

    auto loadX = [&](int ch, float2* xr) {
        const int kk = ch * 16;
        xr[0] = *reinterpret_cast<const float2*>(xp0 + kk);
        xr[1] = *reinterpret_cast<const float2*>(xp1 + kk);
        xr[2] = *reinterpret_cast<const float2*>(xp0 + kk + 8);
        xr[3] = *reinterpret_cast<const float2*>(xp1 + kk + 8);
    };
    auto loadW = [&](int ch, uint4* wr) {
        const uint4* p = wfp + ch * (12 * 32);
#pragma unroll
        for (int q = 0; q < 6; q++) wr[q] = p[q * 32];
    };
    auto compute = [&](const float2* xr, const uint4* wr) {
        uint32_t a[4] = { packh2(xr[0]), packh2(xr[1]), packh2(xr[2]), packh2(xr[3]) };
#pragma unroll
        for (int p = 0; p < 6; p++) {
            const uint32_t* wp = reinterpret_cast<const uint32_t*>(&wr[p]);
            mma16(acc[2 * p],     a, wp);
            mma16(acc[2 * p + 1], a, wp + 2);
        }
    };

    loadX(0, x0); loadW(0, w0);
    loadX(1, x1); loadW(1, w1);
#pragma unroll 1
    for (int ch = 0; ch < 32; ch += 2) {
        compute(x0, w0);
        if (ch + 2 < 32) { loadX(ch + 2, x0); loadW(ch + 2, w0); }
        compute(x1, w1);
        if (ch + 3 < 32) { loadX(ch + 3, x1); loadW(ch + 3, w1); }
    }

    // Route D frags to smem (half)
    {
        const int r0 = rtp + l4, r1 = r0 + 8;
#pragma unroll
        for (int nt = 0; nt < 12; nt++) {
            const int c0 = nb1 + nt * 8 + 2 * lk;
            float d0 = acc[nt][0], d1 = acc[nt][1], d2 = acc[nt][2], d3 = acc[nt][3];
            if (c0 < 64) {
                *reinterpret_cast<uint32_t*>(Qs + r0 * PQH + c0) = packh(d0, d1);
                *reinterpret_cast<uint32_t*>(Qs + r1 * PQH + c0) = packh(d2, d3);
            } else if (c0 < 128) {
                const int c = c0 - 64;
                *reinterpret_cast<uint32_t*>(Ks + r0 * PQH + c) = packh(d0, d1);
                *reinterpret_cast<uint32_t*>(Ks + r1 * PQH + c) = packh(d2, d3);
            } else {
                const int h = c0 - 128;
                Vt[h * PVH + r0]       = __float2half_rn(d0);
                Vt[(h + 1) * PVH + r0] = __float2half_rn(d1);
                Vt[h * PVH + r1]       = __float2half_rn(d2);
                Vt[(h + 1) * PVH + r1] = __float2half_rn(d3);
            }
        }
    }
    __syncthreads();

    // Coalesced copy-out to global fp16 buffers
    {
        const uint32_t* Qw = reinterpret_cast<const uint32_t*>(smem + K_QS);
        const uint32_t* Kw = reinterpret_cast<const uint32_t*>(smem + K_KS);
        const uint32_t* Vw = reinterpret_cast<const uint32_t*>(smem + K_VT);
        const int row = tid >> 2, q = tid & 3;       // Q/K: 128 rows x 4 quads
        {
            const uint4* s = reinterpret_cast<const uint4*>(Qw + row * 36 + q * 8);
            uint4* d = Qg4 + (size_t)b * 1024 + row * 8 + q * 2;
            d[0] = s[0]; d[1] = s[1];
        }
        {
            const uint4* s = reinterpret_cast<const uint4*>(Kw + row * 36 + q * 8);
            uint4* d = Kg4 + (size_t)b * 1024 + row * 8 + q * 2;
            d[0] = s[0]; d[1] = s[1];
        }
        if (tid < 256) {                              // Vt: 64 rows x 4 chunks of 16 u32
            const int vr = tid >> 2, vq = tid & 3;
            const uint4* s = reinterpret_cast<const uint4*>(Vw + vr * 68 + vq * 16);
            uint4* d = Vg4 + (size_t)b * 1024 + vr * 16 + vq * 4;
            d[0] = s[0]; d[1] = s[1]; d[2] = s[2]; d[3] = s[3];
        }
    }
}

// ============================================================================
// Kernel 2: attention, 128 threads, warp W owns row tiles {W, 7-W}
// ============================================================================
template <int W>
__device__ __forceinline__ void attn_warp(const char* smem, int lane, int b,
                                          float* __restrict__ out)
{
    const uint32_t* Qw = reinterpret_cast<const uint32_t*>(smem + K_QS);
    const uint32_t* Kw = reinterpret_cast<const uint32_t*>(smem + K_KS);
    const uint32_t* Vw = reinterpret_cast<const uint32_t*>(smem + K_VT);

    const int l4 = lane >> 2, lk = lane & 3;
    constexpr int RT0 = W * 16, RT1 = (7 - W) * 16;
    constexpr int NT0 = 2 * W + 2;       // S col tiles for rt0
    constexpr int NT1 = 16 - 2 * W;      // S col tiles for rt1  (NT0 <= NT1)
    constexpr int KS0 = W + 1;           // PV k16 steps for rt0
    constexpr int KS1 = 8 - W;           // PV k16 steps for rt1
    const int rA0 = RT0 + l4, rB0 = rA0 + 8;
    const int rA1 = RT1 + l4, rB1 = rA1 + 8;

    // ---- S = Q K^T ----
    float s0[NT0][4], s1[NT1][4];
#pragma unroll
    for (int j = 0; j < NT0; j++)
#pragma unroll
        for (int k = 0; k < 4; k++) s0[j][k] = 0.0f;
#pragma unroll
    for (int j = 0; j < NT1; j++)
#pragma unroll
        for (int k = 0; k < 4; k++) s1[j][k] = 0.0f;

#pragma unroll
    for (int ks = 0; ks < 4; ks++) {
        const int kw = ks * 8 + lk;
        uint32_t a0[4], a1[4];
        {
            const uint32_t* ap = Qw + rA0 * 36 + kw;
            a0[0] = ap[0]; a0[1] = ap[36 * 8]; a0[2] = ap[4]; a0[3] = ap[36 * 8 + 4];
        }
        {
            const uint32_t* ap = Qw + rA1 * 36 + kw;
            a1[0] = ap[0]; a1[1] = ap[36 * 8]; a1[2] = ap[4]; a1[3] = ap[36 * 8 + 4];
        }
#pragma unroll
        for (int nt = 0; nt < NT1; nt++) {
            const uint32_t* bp = Kw + (nt * 8 + l4) * 36 + kw;
            uint32_t b2[2] = { bp[0], bp[4] };
            mma16(s1[nt], a1, b2);
            if (nt < NT0) mma16(s0[nt], a0, b2);
        }
    }

    // ---- softmax (fully warp-local) ----
    float mA0 = -1e30f, mB0 = -1e30f, mA1 = -1e30f, mB1 = -1e30f;
#pragma unroll
    for (int nt = 0; nt < NT0; nt++) {
        const int c0 = nt * 8 + 2 * lk, c1 = c0 + 1;
        s0[nt][0] = (c0 <= rA0) ? s0[nt][0] * 0.125f : -1e30f;
        s0[nt][1] = (c1 <= rA0) ? s0[nt][1] * 0.125f : -1e30f;
        s0[nt][2] = (c0 <= rB0) ? s0[nt][2] * 0.125f : -1e30f;
        s0[nt][3] = (c1 <= rB0) ? s0[nt][3] * 0.125f : -1e30f;
        mA0 = fmaxf(mA0, fmaxf(s0[nt][0], s0[nt][1]));
        mB0 = fmaxf(mB0, fmaxf(s0[nt][2], s0[nt][3]));
    }
#pragma unroll
    for (int nt = 0; nt < NT1; nt++) {
        const int c0 = nt * 8 + 2 * lk, c1 = c0 + 1;
        s1[nt][0] = (c0 <= rA1) ? s1[nt][0] * 0.125f : -1e30f;
        s1[nt][1] = (c1 <= rA1) ? s1[nt][1] * 0.125f : -1e30f;
        s1[nt][2] = (c0 <= rB1) ? s1[nt][2] * 0.125f : -1e30f;
        s1[nt][3] = (c1 <= rB1) ? s1[nt][3] * 0.125f : -1e30f;
        mA1 = fmaxf(mA1, fmaxf(s1[nt][0], s1[nt][1]));
        mB1 = fmaxf(mB1, fmaxf(s1[nt][2], s1[nt][3]));
    }
#pragma unroll
    for (int o = 1; o <= 2; o <<= 1) {
        mA0 = fmaxf(mA0, __shfl_xor_sync(0xffffffffu, mA0, o));
        mB0 = fmaxf(mB0, __shfl_xor_sync(0xffffffffu, mB0, o));
        mA1 = fmaxf(mA1, __shfl_xor_sync(0xffffffffu, mA1, o));
        mB1 = fmaxf(mB1, __shfl_xor_sync(0xffffffffu, mB1, o));
    }
    float sA0 = 0.0f, sB0 = 0.0f, sA1 = 0.0f, sB1 = 0.0f;
#pragma unroll
    for (int nt = 0; nt < NT0; nt++) {
        s0[nt][0] = __expf(s0[nt][0] - mA0); s0[nt][1] = __expf(s0[nt][1] - mA0);
        s0[nt][2] = __expf(s0[nt][2] - mB0); s0[nt][3] = __expf(s0[nt][3] - mB0);
        sA0 += s0[nt][0] + s0[nt][1];
        sB0 += s0[nt][2] + s0[nt][3];
    }
#pragma unroll
    for (int nt = 0; nt < NT1; nt++) {
        s1[nt][0] = __expf(s1[nt][0] - mA1); s1[nt][1] = __expf(s1[nt][1] - mA1);
        s1[nt][2] = __expf(s1[nt][2] - mB1); s1[nt][3] = __expf(s1[nt][3] - mB1);
        sA1 += s1[nt][0] + s1[nt][1];
        sB1 += s1[nt][2] + s1[nt][3];
    }
#pragma unroll
    for (int o = 1; o <= 2; o <<= 1) {
        sA0 += __shfl_xor_sync(0xffffffffu, sA0, o);
        sB0 += __shfl_xor_sync(0xffffffffu, sB0, o);
        sA1 += __shfl_xor_sync(0xffffffffu, sA1, o);
        sB1 += __shfl_xor_sync(0xffffffffu, sB1, o);
    }
    const float invA0 = 1.0f / sA0, invB0 = 1.0f / sB0;
    const float invA1 = 1.0f / sA1, invB1 = 1.0f / sB1;

    // ---- P: D-frag -> fp16 A-frag IN REGISTERS (k-pair == D col-pair) ----
    uint32_t paA[KS0][4], paB[KS1][4];
#pragma unroll
    for (int ks = 0; ks < KS0; ks++) {
        paA[ks][0] = packh(s0[2 * ks][0],     s0[2 * ks][1]);
        paA[ks][1] = packh(s0[2 * ks][2],     s0[2 * ks][3]);
        paA[ks][2] = packh(s0[2 * ks + 1][0], s0[2 * ks + 1][1]);
        paA[ks][3] = packh(s0[2 * ks + 1][2], s0[2 * ks + 1][3]);
    }
#pragma unroll
    for (int ks = 0; ks < KS1; ks++) {
        paB[ks][0] = packh(s1[2 * ks][0],     s1[2 * ks][1]);
        paB[ks][1] = packh(s1[2 * ks][2],     s1[2 * ks][3]);
        paB[ks][2] = packh(s1[2 * ks + 1][0], s1[2 * ks + 1][1]);
        paB[ks][3] = packh(s1[2 * ks + 1][2], s1[2 * ks + 1][3]);
    }

    // ---- O = P @ V ----
    float o0[8][4], o1[8][4];
#pragma unroll
    for (int j = 0; j < 8; j++)
#pragma unroll
        for (int k = 0; k < 4; k++) { o0[j][k] = 0.0f; o1[j][k] = 0.0f; }

#pragma unroll
    for (int ks = 0; ks < KS1; ks++) {
        const int kw = ks * 8 + lk;
#pragma unroll
        for (int nt = 0; nt < 8; nt++) {
            const uint32_t* bp = Vw + (nt * 8 + l4) * 68 + kw;
            uint32_t b2[2] = { bp[0], bp[4] };
            mma16(o1[nt], paB[ks], b2);
            if (ks < KS0) mma16(o0[nt], paA[ks], b2);
        }
    }

    // ---- store, normalized ----
#pragma unroll
    for (int nt = 0; nt < 8; nt++) {
        const int c0 = nt * 8 + 2 * lk;
        *reinterpret_cast<float2*>(out + ((size_t)b * TT + rA0) * HH + c0) =
            make_float2(o0[nt][0] * invA0, o0[nt][1] * invA0);
        *reinterpret_cast<float2*>(out + ((size_t)b * TT + rB0) * HH + c0) =
            make_float2(o0[nt][2] * invB0, o0[nt][3] * invB0);
        *reinterpret_cast<float2*>(out + ((size_t)b * TT + rA1) * HH + c0) =
            make_float2(o1[nt][0] * invA1, o1[nt][1] * invA1);
        *reinterpret_cast<float2*>(out + ((size_t)b * TT + rB1) * HH + c0) =
            make_float2(o1[nt][2] * invB1, o1[nt][3] * invB1);
    }
}

__global__ __launch_bounds__(128)
void attn_kernel(float* __restrict__ out)
{
    extern __shared__ char smem[];
    uint32_t* Qd = reinterpret_cast<uint32_t*>(smem + K_QS);
    uint32_t* Kd = reinterpret_cast<uint32_t*>(smem + K_KS);
    uint32_t* Vd = reinterpret_cast<uint32_t*>(smem + K_VT);

    const int tid  = threadIdx.x;
    const int wid  = tid >> 5;
    const int lane = tid & 31;
    const int b    = blockIdx.x;

    // Load Q, K ([128][32]u32 -> pitch 36) and Vt ([64][64]u32 -> pitch 68)
#pragma unroll
    for (int i = 0; i < 4; i++) {
        const int slot = tid + 128 * i;           // 512 slots
        const int row = slot >> 2, q = slot & 3;
        const uint4* sq = Qg4 + (size_t)b * 1024 + row * 8 + q * 2;
        uint4* dq = reinterpret_cast<uint4*>(Qd + row * 36 + q * 8);
        dq[0] = sq[0]; dq[1] = sq[1];
        const uint4* sk = Kg4 + (size_t)b * 1024 + row * 8 + q * 2;
        uint4* dk = reinterpret_cast<uint4*>(Kd + row * 36 + q * 8);
        dk[0] = sk[0]; dk[1] = sk[1];
    }
#pragma unroll
    for (int i = 0; i < 2; i++) {
        const int slot = tid + 128 * i;           // 256 slots
        const int row = slot >> 2, q = slot & 3;
        const uint4* sv = Vg4 + (size_t)b * 1024 + row * 16 + q * 4;
        uint4* dv = reinterpret_cast<uint4*>(Vd + row * 68 + q * 16);
        dv[0] = sv[0]; dv[1] = sv[1]; dv[2] = sv[2]; dv[3] = sv[3];
    }
    __syncthreads();

    if      (wid == 0) attn_warp<0>(smem, lane, b, out);
    else if (wid == 1) attn_warp<1>(smem, lane, b, out);
    else if (wid == 2) attn_warp<2>(smem, lane, b, out);
    else               attn_warp<3>(smem, lane, b, out);
}

extern "C" void kernel_launch(void* const* d_in, const int* in_sizes, int n_in,
                              void* d_out, int out_size)
{
    const float* x  = (const float*)d_in[0];
    const float* Wq = (const float*)d_in[1];
    const float* Wk = (const float*)d_in[2];
    const float* Wv = (const float*)d_in[3];
    float* out = (float*)d_out;

    const int B = in_sizes[0] / (TT * CC);   // 512

    convwf_kernel<<<384, 32>>>(Wq, Wk, Wv);

    cudaFuncSetAttribute(proj_kernel,
                         cudaFuncAttributeMaxDynamicSharedMemorySize, K_SMEM);
    proj_kernel<<<B, 512, K_SMEM>>>(x);

    cudaFuncSetAttribute(attn_kernel,
                         cudaFuncAttributeMaxDynamicSharedMemorySize, K_SMEM);
    attn_kernel<<<B, 128, K_SMEM>>>(out);
}

// round 16
// speedup vs baseline: 1.0568x; 1.0568x over previous
#include <cuda_runtime.h>
#include <cuda_fp16.h>
#include <cstdint>

// x [B=512, T=128, C=512] fp32; Wq/Wk/Wv [H=64, C=512]; out [B, T, 64] fp32.
// Round-16: ONE kernel = round-12 projection (verbatim, 512 thr) +
// barrier-free warp-local attention (warps 0-7 own full row tiles; P never
// leaves registers: fp32 D-frag col-pairs pack directly into fp16 A-frag
// k-pairs inside the PV loop).
#define TT 128
#define CC 512
#define HH 64

#define PQH 72    // Q/K smem [128][64] half (36 u32 pitch)
#define PVH 136   // Vt smem [64][128] half (68 u32 pitch)

#define K_QS 0
#define K_KS 18432
#define K_VT 36864
#define K_SMEM 54272

__device__ uint4 Wfg[32 * 12 * 32];   // pre-fragmented fp16 W B-frags

__device__ __forceinline__ uint32_t packh(float lo, float hi) {
    __half2 h = __floats2half2_rn(lo, hi);
    return *reinterpret_cast<uint32_t*>(&h);
}
__device__ __forceinline__ uint32_t packh2(float2 v) { return packh(v.x, v.y); }

__device__ __forceinline__ void mma16(float* d, const uint32_t* a, const uint32_t* b) {
    asm volatile(
        "mma.sync.aligned.m16n8k16.row.col.f32.f16.f16.f32 "
        "{%0,%1,%2,%3}, {%4,%5,%6,%7}, {%8,%9}, {%0,%1,%2,%3};"
        : "+f"(d[0]), "+f"(d[1]), "+f"(d[2]), "+f"(d[3])
        : "r"(a[0]), "r"(a[1]), "r"(a[2]), "r"(a[3]), "r"(b[0]), "r"(b[1]));
}

// ------- pre-kernel: W fp32 -> fp16 B-fragments in global -------
__global__ void convwf_kernel(const float* __restrict__ Wq,
                              const float* __restrict__ Wk,
                              const float* __restrict__ Wv)
{
    const int blk  = blockIdx.x;        // ch*12 + np
    const int ch   = blk / 12;
    const int np   = blk % 12;
    const int lane = threadIdx.x;
    const int l4   = lane >> 2;
    const int lk   = lane & 3;
    const int kk   = ch * 16;

    auto wrow = [&](int j) -> const float* {
        return (j < 64) ? (Wq + j * CC)
             : (j < 128) ? (Wk + (j - 64) * CC)
                         : (Wv + (j - 128) * CC);
    };
    const float* r0 = wrow((2 * np) * 8 + l4);
    const float* r1 = wrow((2 * np + 1) * 8 + l4);

    uint4 v;
    v.x = packh2(*reinterpret_cast<const float2*>(r0 + kk + 2 * lk));
    v.y = packh2(*reinterpret_cast<const float2*>(r0 + kk + 2 * lk + 8));
    v.z = packh2(*reinterpret_cast<const float2*>(r1 + kk + 2 * lk));
    v.w = packh2(*reinterpret_cast<const float2*>(r1 + kk + 2 * lk + 8));
    Wfg[blk * 32 + lane] = v;
}

// ------- attention, warp-local: warp W owns row tile W (rows 16W..16W+15) ----
template <int W>
__device__ __forceinline__ void attn_warp(const char* smem, int lane, int b,
                                          float* __restrict__ out)
{
    const uint32_t* Qw = reinterpret_cast<const uint32_t*>(smem + K_QS);
    const uint32_t* Kw = reinterpret_cast<const uint32_t*>(smem + K_KS);
    const uint32_t* Vw = reinterpret_cast<const uint32_t*>(smem + K_VT);

    const int l4 = lane >> 2, lk = lane & 3;
    constexpr int RT = W * 16;
    constexpr int NT = 2 * W + 2;       // S col tiles (causal)
    constexpr int KS = W + 1;           // PV k16 steps
    const int rA = RT + l4, rB = rA + 8;

    // ---- S = Q K^T ----
    float s[NT][4];
#pragma unroll
    for (int j = 0; j < NT; j++)
#pragma unroll
        for (int k = 0; k < 4; k++) s[j][k] = 0.0f;

#pragma unroll
    for (int ks = 0; ks < 4; ks++) {
        const int kw = ks * 8 + lk;
        uint32_t a[4];
        const uint32_t* ap = Qw + rA * 36 + kw;
        a[0] = ap[0]; a[1] = ap[36 * 8]; a[2] = ap[4]; a[3] = ap[36 * 8 + 4];
#pragma unroll
        for (int nt = 0; nt < NT; nt++) {
            const uint32_t* bp = Kw + (nt * 8 + l4) * 36 + kw;
            uint32_t b2[2] = { bp[0], bp[4] };
            mma16(s[nt], a, b2);
        }
    }

    // ---- warp-local softmax (rows live on 4 lanes -> 2 shuffles) ----
    float mA = -1e30f, mB = -1e30f;
#pragma unroll
    for (int nt = 0; nt < NT; nt++) {
        const int c0 = nt * 8 + 2 * lk, c1 = c0 + 1;
        s[nt][0] = (c0 <= rA) ? s[nt][0] * 0.125f : -1e30f;
        s[nt][1] = (c1 <= rA) ? s[nt][1] * 0.125f : -1e30f;
        s[nt][2] = (c0 <= rB) ? s[nt][2] * 0.125f : -1e30f;
        s[nt][3] = (c1 <= rB) ? s[nt][3] * 0.125f : -1e30f;
        mA = fmaxf(mA, fmaxf(s[nt][0], s[nt][1]));
        mB = fmaxf(mB, fmaxf(s[nt][2], s[nt][3]));
    }
#pragma unroll
    for (int o = 1; o <= 2; o <<= 1) {
        mA = fmaxf(mA, __shfl_xor_sync(0xffffffffu, mA, o));
        mB = fmaxf(mB, __shfl_xor_sync(0xffffffffu, mB, o));
    }
    float sA = 0.0f, sB = 0.0f;
#pragma unroll
    for (int nt = 0; nt < NT; nt++) {
        s[nt][0] = __expf(s[nt][0] - mA); s[nt][1] = __expf(s[nt][1] - mA);
        s[nt][2] = __expf(s[nt][2] - mB); s[nt][3] = __expf(s[nt][3] - mB);
        sA += s[nt][0] + s[nt][1];
        sB += s[nt][2] + s[nt][3];
    }
#pragma unroll
    for (int o = 1; o <= 2; o <<= 1) {
        sA += __shfl_xor_sync(0xffffffffu, sA, o);
        sB += __shfl_xor_sync(0xffffffffu, sB, o);
    }
    const float invA = 1.0f / sA, invB = 1.0f / sB;

    // ---- O = P @ V ; P packed on the fly (D col-pairs == A k-pairs) ----
    float o[8][4];
#pragma unroll
    for (int j = 0; j < 8; j++)
#pragma unroll
        for (int k = 0; k < 4; k++) o[j][k] = 0.0f;

#pragma unroll
    for (int ks = 0; ks < KS; ks++) {
        uint32_t a[4];
        a[0] = packh(s[2 * ks][0],     s[2 * ks][1]);
        a[1] = packh(s[2 * ks][2],     s[2 * ks][3]);
        a[2] = packh(s[2 * ks + 1][0], s[2 * ks + 1][1]);
        a[3] = packh(s[2 * ks + 1][2], s[2 * ks + 1][3]);
        const int kw = ks * 8 + lk;
#pragma unroll
        for (int nt = 0; nt < 8; nt++) {
            const uint32_t* bp = Vw + (nt * 8 + l4) * 68 + kw;
            uint32_t b2[2] = { bp[0], bp[4] };
            mma16(o[nt], a, b2);
        }
    }

    // ---- store, normalized ----
#pragma unroll
    for (int nt = 0; nt < 8; nt++) {
        const int c0 = nt * 8 + 2 * lk;
        *reinterpret_cast<float2*>(out + ((size_t)b * TT + rA) * HH + c0) =
            make_float2(o[nt][0] * invA, o[nt][1] * invA);
        *reinterpret_cast<float2*>(out + ((size_t)b * TT + rB) * HH + c0) =
            make_float2(o[nt][2] * invB, o[nt][3] * invB);
    }
}

// ============================================================================
// Fused kernel: r12 projection (512 thr) + barrier-free attention (warps 0-7)
// ============================================================================
__global__ __launch_bounds__(512, 1)
void attn_fused16_kernel(const float* __restrict__ x, float* __restrict__ out)
{
    extern __shared__ char smem[];
    __half* Qs = reinterpret_cast<__half*>(smem + K_QS);
    __half* Ks = reinterpret_cast<__half*>(smem + K_KS);
    __half* Vt = reinterpret_cast<__half*>(smem + K_VT);

    const int tid  = threadIdx.x;
    const int wid  = tid >> 5;
    const int lane = tid & 31;
    const int l4   = lane >> 2;
    const int lk   = lane & 3;
    const int b    = blockIdx.x;
    const float* xb = x + (size_t)b * TT * CC;

    // ---------- projection: warp = 1 row-tile x col-half (r12 verbatim) -------
    const int rtp = (wid >> 1) * 16;
    const int wcp = wid & 1;
    const int nb1 = wcp * 96;

    float acc[12][4];
#pragma unroll
    for (int j = 0; j < 12; j++)
#pragma unroll
        for (int k = 0; k < 4; k++) acc[j][k] = 0.0f;

    const float* xp0 = xb + (rtp + l4) * CC + 2 * lk;
    const float* xp1 = xb + (rtp + 8 + l4) * CC + 2 * lk;
    const uint4* wfp = Wfg + (wcp * 6) * 32 + lane;

    float2 x0[4], x1[4];
    uint4  w0[6], w1[6];

    auto loadX = [&](int ch, float2* xr) {
        const int kk = ch * 16;
        xr[0] = *reinterpret_cast<const float2*>(xp0 + kk);
        xr[1] = *reinterpret_cast<const float2*>(xp1 + kk);
        xr[2] = *reinterpret_cast<const float2*>(xp0 + kk + 8);
        xr[3] = *reinterpret_cast<const float2*>(xp1 + kk + 8);
    };
    auto loadW = [&](int ch, uint4* wr) {
        const uint4* p = wfp + ch * (12 * 32);
#pragma unroll
        for (int q = 0; q < 6; q++) wr[q] = p[q * 32];
    };
    auto compute = [&](const float2* xr, const uint4* wr) {
        uint32_t a[4] = { packh2(xr[0]), packh2(xr[1]), packh2(xr[2]), packh2(xr[3]) };
#pragma unroll
        for (int p = 0; p < 6; p++) {
            const uint32_t* wp = reinterpret_cast<const uint32_t*>(&wr[p]);
            mma16(acc[2 * p],     a, wp);
            mma16(acc[2 * p + 1], a, wp + 2);
        }
    };

    loadX(0, x0); loadW(0, w0);
    loadX(1, x1); loadW(1, w1);
#pragma unroll 1
    for (int ch = 0; ch < 32; ch += 2) {
        compute(x0, w0);
        if (ch + 2 < 32) { loadX(ch + 2, x0); loadW(ch + 2, w0); }
        compute(x1, w1);
        if (ch + 3 < 32) { loadX(ch + 3, x1); loadW(ch + 3, w1); }
    }

    // ---------- epilogue: route D frags to Qs / Ks / Vt ----------
    {
        const int r0 = rtp + l4, r1 = r0 + 8;
#pragma unroll
        for (int nt = 0; nt < 12; nt++) {
            const int c0 = nb1 + nt * 8 + 2 * lk;
            float d0 = acc[nt][0], d1 = acc[nt][1], d2 = acc[nt][2], d3 = acc[nt][3];
            if (c0 < 64) {
                *reinterpret_cast<uint32_t*>(Qs + r0 * PQH + c0) = packh(d0, d1);
                *reinterpret_cast<uint32_t*>(Qs + r1 * PQH + c0) = packh(d2, d3);
            } else if (c0 < 128) {
                const int c = c0 - 64;
                *reinterpret_cast<uint32_t*>(Ks + r0 * PQH + c) = packh(d0, d1);
                *reinterpret_cast<uint32_t*>(Ks + r1 * PQH + c) = packh(d2, d3);
            } else {
                const int h = c0 - 128;
                Vt[h * PVH + r0]       = __float2half_rn(d0);
                Vt[(h + 1) * PVH + r0] = __float2half_rn(d1);
                Vt[h * PVH + r1]       = __float2half_rn(d2);
                Vt[(h + 1) * PVH + r1] = __float2half_rn(d3);
            }
        }
    }
    __syncthreads();   // the ONLY barrier

    // ---------- attention: warps 0-7 own row tiles 0-7, fully warp-local -----
    switch (wid) {
        case 0: attn_warp<0>(smem, lane, b, out); break;
        case 1: attn_warp<1>(smem, lane, b, out); break;
        case 2: attn_warp<2>(smem, lane, b, out); break;
        case 3: attn_warp<3>(smem, lane, b, out); break;
        case 4: attn_warp<4>(smem, lane, b, out); break;
        case 5: attn_warp<5>(smem, lane, b, out); break;
        case 6: attn_warp<6>(smem, lane, b, out); break;
        case 7: attn_warp<7>(smem, lane, b, out); break;
        default: break;   // warps 8-15 done
    }
}

extern "C" void kernel_launch(void* const* d_in, const int* in_sizes, int n_in,
                              void* d_out, int out_size)
{
    const float* x  = (const float*)d_in[0];
    const float* Wq = (const float*)d_in[1];
    const float* Wk = (const float*)d_in[2];
    const float* Wv = (const float*)d_in[3];
    float* out = (float*)d_out;

    const int B = in_sizes[0] / (TT * CC);   // 512

    convwf_kernel<<<384, 32>>>(Wq, Wk, Wv);

    cudaFuncSetAttribute(attn_fused16_kernel,
                         cudaFuncAttributeMaxDynamicSharedMemorySize, K_SMEM);
    attn_fused16_kernel<<<B, 512, K_SMEM>>>(x, out);
}

// round 17
// speedup vs baseline: 1.2275x; 1.1615x over previous
#include <cuda_runtime.h>
#include <cuda_fp16.h>
#include <cstdint>

// x [B=512, T=128, C=512] fp32; Wq/Wk/Wv [H=64, C=512]; out [B, T, 64] fp32.
// Round-17: round-12 champion + cache-policy hints only:
//   X loads  -> __ldcs (streaming, evict-first; stop thrashing Wfg out of L1)
//   W loads  -> __ldg  (read-only cached)
//   out store-> __stcs (streaming; out never re-read)
#define TT 128
#define CC 512
#define HH 64
#define NTH 512

#define PQH 72    // Qs/Ks [128][64] half (36 u32 pitch)
#define PVH 136   // Vt [64][128] half  (68 u32 pitch)
#define PPH 136   // P  [128][128] half

#define OFF_QS  0
#define OFF_KS  18432
#define OFF_VT  36864
#define OFF_P   54272
#define OFF_RED 89088            // pmax [4][128] f32 + psum [4][128] f32
#define SMEM_BYTES 93184

// Pre-fragmented fp16 W: Wfg[ch(32)][npair(12)][lane(32)] = uint4
__device__ uint4 Wfg[32 * 12 * 32];

__device__ __forceinline__ uint32_t packh(float lo, float hi) {
    __half2 h = __floats2half2_rn(lo, hi);
    return *reinterpret_cast<uint32_t*>(&h);
}
__device__ __forceinline__ uint32_t packh2(float2 v) { return packh(v.x, v.y); }

__device__ __forceinline__ void mma16(float* d, const uint32_t* a, const uint32_t* b) {
    asm volatile(
        "mma.sync.aligned.m16n8k16.row.col.f32.f16.f16.f32 "
        "{%0,%1,%2,%3}, {%4,%5,%6,%7}, {%8,%9}, {%0,%1,%2,%3};"
        : "+f"(d[0]), "+f"(d[1]), "+f"(d[2]), "+f"(d[3])
        : "r"(a[0]), "r"(a[1]), "r"(a[2]), "r"(a[3]), "r"(b[0]), "r"(b[1]));
}

// ------- pre-kernel: W fp32 -> fp16 B-fragments in global -------
__global__ void convwf_kernel(const float* __restrict__ Wq,
                              const float* __restrict__ Wk,
                              const float* __restrict__ Wv)
{
    const int blk  = blockIdx.x;        // 0..383 = ch*12 + np
    const int ch   = blk / 12;
    const int np   = blk % 12;
    const int lane = threadIdx.x;       // 32 threads
    const int l4   = lane >> 2;
    const int lk   = lane & 3;
    const int kk   = ch * 16;

    auto wrow = [&](int j) -> const float* {
        return (j < 64) ? (Wq + j * CC)
             : (j < 128) ? (Wk + (j - 64) * CC)
                         : (Wv + (j - 128) * CC);
    };
    const float* r0 = wrow((2 * np) * 8 + l4);
    const float* r1 = wrow((2 * np + 1) * 8 + l4);

    uint4 v;
    v.x = packh2(*reinterpret_cast<const float2*>(r0 + kk + 2 * lk));
    v.y = packh2(*reinterpret_cast<const float2*>(r0 + kk + 2 * lk + 8));
    v.z = packh2(*reinterpret_cast<const float2*>(r1 + kk + 2 * lk));
    v.w = packh2(*reinterpret_cast<const float2*>(r1 + kk + 2 * lk + 8));
    Wfg[blk * 32 + lane] = v;
}

__global__ __launch_bounds__(NTH, 1)
void attn_fp16r_kernel(const float* __restrict__ x, float* __restrict__ out)
{
    extern __shared__ char smem[];
    __half* Qs = reinterpret_cast<__half*>(smem + OFF_QS);
    __half* Ks = reinterpret_cast<__half*>(smem + OFF_KS);
    __half* Vt = reinterpret_cast<__half*>(smem + OFF_VT);
    __half* Ph = reinterpret_cast<__half*>(smem + OFF_P);
    float*  pm = reinterpret_cast<float*>(smem + OFF_RED);          // [4][128]
    float*  ps = reinterpret_cast<float*>(smem + OFF_RED + 2048);   // [4][128]
    const uint32_t* Qw = reinterpret_cast<const uint32_t*>(smem + OFF_QS);
    const uint32_t* Kw = reinterpret_cast<const uint32_t*>(smem + OFF_KS);
    const uint32_t* Vw = reinterpret_cast<const uint32_t*>(smem + OFF_VT);
    const uint32_t* Pw = reinterpret_cast<const uint32_t*>(smem + OFF_P);

    const int tid  = threadIdx.x;
    const int wid  = tid >> 5;
    const int lane = tid & 31;
    const int l4   = lane >> 2;
    const int lk   = lane & 3;
    const int b    = blockIdx.x;
    const float* xb = x + (size_t)b * TT * CC;

    // ---------- Phase 1 ownership: 8 row-tiles x 2 col-halves ----------
    const int rtp = (wid >> 1) * 16;        // row tile (m16)
    const int wcp = wid & 1;                // col half: 96 n-cols
    const int nb1 = wcp * 96;

    float acc[12][4];
#pragma unroll
    for (int j = 0; j < 12; j++)
#pragma unroll
        for (int k = 0; k < 4; k++) acc[j][k] = 0.0f;

    const float* xp0 = xb + (rtp + l4) * CC + 2 * lk;        // row r0
    const float* xp1 = xb + (rtp + 8 + l4) * CC + 2 * lk;    // row r0+8
    const uint4* wfp = Wfg + (wcp * 6) * 32 + lane;          // + ch*12*32

    float2 x0[4], x1[4];
    uint4  w0[6], w1[6];

    auto loadX = [&](int ch, float2* xr) {
        const int kk = ch * 16;
        xr[0] = __ldcs(reinterpret_cast<const float2*>(xp0 + kk));
        xr[1] = __ldcs(reinterpret_cast<const float2*>(xp1 + kk));
        xr[2] = __ldcs(reinterpret_cast<const float2*>(xp0 + kk + 8));
        xr[3] = __ldcs(reinterpret_cast<const float2*>(xp1 + kk + 8));
    };
    auto loadW = [&](int ch, uint4* wr) {
        const uint4* p = wfp + ch * (12 * 32);
#pragma unroll
        for (int q = 0; q < 6; q++) wr[q] = __ldg(p + q * 32);
    };
    auto compute = [&](const float2* xr, const uint4* wr) {
        uint32_t a[4] = { packh2(xr[0]), packh2(xr[1]), packh2(xr[2]), packh2(xr[3]) };
#pragma unroll
        for (int p = 0; p < 6; p++) {
            const uint32_t* wp = reinterpret_cast<const uint32_t*>(&wr[p]);
            mma16(acc[2 * p],     a, wp);
            mma16(acc[2 * p + 1], a, wp + 2);
        }
    };

    loadX(0, x0); loadW(0, w0);
    loadX(1, x1); loadW(1, w1);
#pragma unroll 1
    for (int ch = 0; ch < 32; ch += 2) {
        compute(x0, w0);
        if (ch + 2 < 32) { loadX(ch + 2, x0); loadW(ch + 2, w0); }
        compute(x1, w1);
        if (ch + 3 < 32) { loadX(ch + 3, x1); loadW(ch + 3, w1); }
    }

    // Epilogue: route D frags to Qs / Ks (half) and Vt (half, transposed)
    {
        const int r0 = rtp + l4, r1 = r0 + 8;
#pragma unroll
        for (int nt = 0; nt < 12; nt++) {
            const int c0 = nb1 + nt * 8 + 2 * lk;
            float d0 = acc[nt][0], d1 = acc[nt][1], d2 = acc[nt][2], d3 = acc[nt][3];
            if (c0 < 64) {
                *reinterpret_cast<uint32_t*>(Qs + r0 * PQH + c0) = packh(d0, d1);
                *reinterpret_cast<uint32_t*>(Qs + r1 * PQH + c0) = packh(d2, d3);
            } else if (c0 < 128) {
                const int c = c0 - 64;
                *reinterpret_cast<uint32_t*>(Ks + r0 * PQH + c) = packh(d0, d1);
                *reinterpret_cast<uint32_t*>(Ks + r1 * PQH + c) = packh(d2, d3);
            } else {
                const int h = c0 - 128;
                Vt[h * PVH + r0]       = __float2half_rn(d0);
                Vt[(h + 1) * PVH + r0] = __float2half_rn(d1);
                Vt[h * PVH + r1]       = __float2half_rn(d2);
                Vt[(h + 1) * PVH + r1] = __float2half_rn(d3);
            }
        }
    }
    __syncthreads();

    // ---------- Attention ownership: 4 row-pairs x 4 col-groups ----------
    const int wr2 = wid >> 2;               // 0..3 : rows {wr2, 7-wr2}
    const int wc2 = wid & 3;                // 0..3
    const int rt0 = wr2 * 16;
    const int rt1 = (7 - wr2) * 16;
    const int rA0 = rt0 + l4, rB0 = rA0 + 8;
    const int rA1 = rt1 + l4, rB1 = rA1 + 8;
    float invA0, invB0, invA1, invB1;

    // ============ Phase 2: S = Q K^T + in-register softmax ============
    {
        const int ntmax0 = 2 * wr2 + 1;
        const int ntmax1 = 15 - 2 * wr2;
        float accS0[4][4], accS1[4][4];
#pragma unroll
        for (int j = 0; j < 4; j++)
#pragma unroll
            for (int k = 0; k < 4; k++) { accS0[j][k] = 0.0f; accS1[j][k] = 0.0f; }

#pragma unroll
        for (int ks = 0; ks < 4; ks++) {
            const int kw = ks * 8 + lk;
            uint32_t a0[4], a1[4];
            {
                const uint32_t* ap = Qw + rA0 * 36 + kw;
                a0[0] = ap[0]; a0[1] = ap[36 * 8];
                a0[2] = ap[4]; a0[3] = ap[36 * 8 + 4];
            }
            {
                const uint32_t* ap = Qw + rA1 * 36 + kw;
                a1[0] = ap[0]; a1[1] = ap[36 * 8];
                a1[2] = ap[4]; a1[3] = ap[36 * 8 + 4];
            }
#pragma unroll
            for (int u = 0; u < 4; u++) {
                const int nt = wc2 + 4 * u;
                if (nt <= ntmax1) {
                    const uint32_t* bp = Kw + (nt * 8 + l4) * 36 + kw;
                    uint32_t b2[2] = { bp[0], bp[4] };
                    mma16(accS1[u], a1, b2);
                    if (nt <= ntmax0) mma16(accS0[u], a0, b2);
                }
            }
        }

        // mask + scale in registers, partial row maxima
        float mA0 = -1e30f, mB0 = -1e30f, mA1 = -1e30f, mB1 = -1e30f;
#pragma unroll
        for (int u = 0; u < 4; u++) {
            const int c0 = (wc2 + 4 * u) * 8 + 2 * lk, c1 = c0 + 1;
            accS0[u][0] = (c0 <= rA0) ? accS0[u][0] * 0.125f : -1e30f;
            accS0[u][1] = (c1 <= rA0) ? accS0[u][1] * 0.125f : -1e30f;
            accS0[u][2] = (c0 <= rB0) ? accS0[u][2] * 0.125f : -1e30f;
            accS0[u][3] = (c1 <= rB0) ? accS0[u][3] * 0.125f : -1e30f;
            accS1[u][0] = (c0 <= rA1) ? accS1[u][0] * 0.125f : -1e30f;
            accS1[u][1] = (c1 <= rA1) ? accS1[u][1] * 0.125f : -1e30f;
            accS1[u][2] = (c0 <= rB1) ? accS1[u][2] * 0.125f : -1e30f;
            accS1[u][3] = (c1 <= rB1) ? accS1[u][3] * 0.125f : -1e30f;
            mA0 = fmaxf(mA0, fmaxf(accS0[u][0], accS0[u][1]));
            mB0 = fmaxf(mB0, fmaxf(accS0[u][2], accS0[u][3]));
            mA1 = fmaxf(mA1, fmaxf(accS1[u][0], accS1[u][1]));
            mB1 = fmaxf(mB1, fmaxf(accS1[u][2], accS1[u][3]));
        }
#pragma unroll
        for (int o = 1; o <= 2; o <<= 1) {
            mA0 = fmaxf(mA0, __shfl_xor_sync(0xffffffffu, mA0, o));
            mB0 = fmaxf(mB0, __shfl_xor_sync(0xffffffffu, mB0, o));
            mA1 = fmaxf(mA1, __shfl_xor_sync(0xffffffffu, mA1, o));
            mB1 = fmaxf(mB1, __shfl_xor_sync(0xffffffffu, mB1, o));
        }
        if (lk == 0) {
            pm[wc2 * 128 + rA0] = mA0; pm[wc2 * 128 + rB0] = mB0;
            pm[wc2 * 128 + rA1] = mA1; pm[wc2 * 128 + rB1] = mB1;
        }
        __syncthreads();
        mA0 = fmaxf(fmaxf(pm[rA0], pm[128 + rA0]), fmaxf(pm[256 + rA0], pm[384 + rA0]));
        mB0 = fmaxf(fmaxf(pm[rB0], pm[128 + rB0]), fmaxf(pm[256 + rB0], pm[384 + rB0]));
        mA1 = fmaxf(fmaxf(pm[rA1], pm[128 + rA1]), fmaxf(pm[256 + rA1], pm[384 + rA1]));
        mB1 = fmaxf(fmaxf(pm[rB1], pm[128 + rB1]), fmaxf(pm[256 + rB1], pm[384 + rB1]));

        // exp, partial sums, write unnormalized P (fp16)
        float sA0 = 0.0f, sB0 = 0.0f, sA1 = 0.0f, sB1 = 0.0f;
#pragma unroll
        for (int u = 0; u < 4; u++) {
            const int c0 = (wc2 + 4 * u) * 8 + 2 * lk;
            float e0 = __expf(accS0[u][0] - mA0), e1 = __expf(accS0[u][1] - mA0);
            float e2 = __expf(accS0[u][2] - mB0), e3 = __expf(accS0[u][3] - mB0);
            float f0 = __expf(accS1[u][0] - mA1), f1 = __expf(accS1[u][1] - mA1);
            float f2 = __expf(accS1[u][2] - mB1), f3 = __expf(accS1[u][3] - mB1);
            sA0 += e0 + e1; sB0 += e2 + e3;
            sA1 += f0 + f1; sB1 += f2 + f3;
            *reinterpret_cast<uint32_t*>(Ph + rA0 * PPH + c0) = packh(e0, e1);
            *reinterpret_cast<uint32_t*>(Ph + rB0 * PPH + c0) = packh(e2, e3);
            *reinterpret_cast<uint32_t*>(Ph + rA1 * PPH + c0) = packh(f0, f1);
            *reinterpret_cast<uint32_t*>(Ph + rB1 * PPH + c0) = packh(f2, f3);
        }
#pragma unroll
        for (int o = 1; o <= 2; o <<= 1) {
            sA0 += __shfl_xor_sync(0xffffffffu, sA0, o);
            sB0 += __shfl_xor_sync(0xffffffffu, sB0, o);
            sA1 += __shfl_xor_sync(0xffffffffu, sA1, o);
            sB1 += __shfl_xor_sync(0xffffffffu, sB1, o);
        }
        if (lk == 0) {
            ps[wc2 * 128 + rA0] = sA0; ps[wc2 * 128 + rB0] = sB0;
            ps[wc2 * 128 + rA1] = sA1; ps[wc2 * 128 + rB1] = sB1;
        }
        __syncthreads();     // psum + P visible to all warps
        invA0 = 1.0f / (ps[rA0] + ps[128 + rA0] + ps[256 + rA0] + ps[384 + rA0]);
        invB0 = 1.0f / (ps[rB0] + ps[128 + rB0] + ps[256 + rB0] + ps[384 + rB0]);
        invA1 = 1.0f / (ps[rA1] + ps[128 + rA1] + ps[256 + rA1] + ps[384 + rA1]);
        invB1 = 1.0f / (ps[rB1] + ps[128 + rB1] + ps[256 + rB1] + ps[384 + rB1]);
    }

    // ============ Phase 3: O = P @ V — causal k-skip, normalize at store ============
    {
        const int nb3 = wc2 * 16;            // 2 n-tiles of 8 cols
        const int ksmax0 = wr2;
        const int ksmax1 = 7 - wr2;
        float accO[2][2][4];
#pragma unroll
        for (int i = 0; i < 2; i++)
#pragma unroll
            for (int j = 0; j < 2; j++)
#pragma unroll
                for (int k = 0; k < 4; k++) accO[i][j][k] = 0.0f;

#pragma unroll
        for (int ks = 0; ks < 8; ks++) {
            if (ks <= ksmax1) {
                const int kw = ks * 8 + lk;
                uint32_t b2[2][2];
#pragma unroll
                for (int nt = 0; nt < 2; nt++) {
                    const uint32_t* bp = Vw + (nb3 + nt * 8 + l4) * 68 + kw;
                    b2[nt][0] = bp[0]; b2[nt][1] = bp[4];
                }
                uint32_t a1[4];
                {
                    const uint32_t* ap = Pw + rA1 * 68 + kw;
                    a1[0] = ap[0]; a1[1] = ap[68 * 8];
                    a1[2] = ap[4]; a1[3] = ap[68 * 8 + 4];
                }
                mma16(accO[1][0], a1, b2[0]);
                mma16(accO[1][1], a1, b2[1]);
                if (ks <= ksmax0) {
                    uint32_t a0[4];
                    const uint32_t* ap = Pw + rA0 * 68 + kw;
                    a0[0] = ap[0]; a0[1] = ap[68 * 8];
                    a0[2] = ap[4]; a0[3] = ap[68 * 8 + 4];
                    mma16(accO[0][0], a0, b2[0]);
                    mma16(accO[0][1], a0, b2[1]);
                }
            }
        }

#pragma unroll
        for (int mt = 0; mt < 2; mt++) {
            const int r0 = (mt ? rA1 : rA0);
            const float ia = mt ? invA1 : invA0;
            const float ib = mt ? invB1 : invB0;
#pragma unroll
            for (int nt = 0; nt < 2; nt++) {
                const int c0 = nb3 + nt * 8 + 2 * lk;
                __stcs(reinterpret_cast<float2*>(out + ((size_t)b * TT + r0) * HH + c0),
                       make_float2(accO[mt][nt][0] * ia, accO[mt][nt][1] * ia));
                __stcs(reinterpret_cast<float2*>(out + ((size_t)b * TT + r0 + 8) * HH + c0),
                       make_float2(accO[mt][nt][2] * ib, accO[mt][nt][3] * ib));
            }
        }
    }
}

extern "C" void kernel_launch(void* const* d_in, const int* in_sizes, int n_in,
                              void* d_out, int out_size)
{
    const float* x  = (const float*)d_in[0];
    const float* Wq = (const float*)d_in[1];
    const float* Wk = (const float*)d_in[2];
    const float* Wv = (const float*)d_in[3];
    float* out = (float*)d_out;

    const int B = in_sizes[0] / (TT * CC);   // 512

    convwf_kernel<<<384, 32>>>(Wq, Wk, Wv);

    cudaFuncSetAttribute(attn_fp16r_kernel,
                         cudaFuncAttributeMaxDynamicSharedMemorySize, SMEM_BYTES);
    attn_fp16r_kernel<<<B, NTH, SMEM_BYTES>>>(x, out);
}